// round 1
// baseline (speedup 1.0000x reference)
#include <cuda_runtime.h>
#include <math.h>

#define NN 1024
#define LL 2048
#define HH 128
#define H3 384
#define STEPS 2

// ---------------- device scratch (no allocations allowed) ----------------
__device__ float g_x[NN*HH];        // decoder input (ones for step 0)
__device__ float g_state[NN*HH];    // GRU hidden state
__device__ float g_q[NN*HH];        // q = state @ Wq^T
__device__ float g_logits[NN*LL];   // attention logits per step
__device__ float g_WkT[HH*HH];      // WkT[j][o] = Wk[o][j]
__device__ float g_WihT[HH*H3];     // WihT[j][g] = W_ih[g][j]
__device__ float g_WhhT[HH*H3];
__device__ float g_WqT[HH*HH];      // WqT[j][o] = Wq[o][j]

// ---------------- init: set x=1, copy state, transpose weights -----------
__global__ void init_kernel(const float* __restrict__ state,
                            const float* __restrict__ W_ih,
                            const float* __restrict__ W_hh,
                            const float* __restrict__ Wq,
                            const float* __restrict__ Wk) {
    int i = blockIdx.x * blockDim.x + threadIdx.x;
    int stride = gridDim.x * blockDim.x;
    for (int idx = i; idx < NN*HH; idx += stride) {
        g_x[idx] = 1.0f;
        g_state[idx] = state[idx];
    }
    for (int idx = i; idx < H3*HH; idx += stride) {
        int g = idx / HH, j = idx % HH;
        g_WihT[j*H3 + g] = W_ih[idx];
        g_WhhT[j*H3 + g] = W_hh[idx];
    }
    for (int idx = i; idx < HH*HH; idx += stride) {
        int h = idx / HH, j = idx % HH;
        g_WkT[j*HH + h] = Wk[idx];
        g_WqT[j*HH + h] = Wq[idx];
    }
}

// ---------------- GRU cell + q projection (8 rows per block) -------------
__global__ void gru_q_kernel(const float* __restrict__ b_ih,
                             const float* __restrict__ b_hh) {
    const int h  = threadIdx.x;          // 0..127
    const int nb = blockIdx.x * 8;
    __shared__ float xs[8][HH];
    __shared__ float hs[8][HH];
    #pragma unroll
    for (int r = 0; r < 8; r++) {
        xs[r][h] = g_x[(nb + r)*HH + h];
        hs[r][h] = g_state[(nb + r)*HH + h];
    }
    __syncthreads();

    float ar[8], az[8], an_[8], br[8], bz[8], bn[8];
    const float bi_r = b_ih[h], bi_z = b_ih[HH+h], bi_n = b_ih[2*HH+h];
    const float bh_r = b_hh[h], bh_z = b_hh[HH+h], bh_n = b_hh[2*HH+h];
    #pragma unroll
    for (int r = 0; r < 8; r++) {
        ar[r]=bi_r; az[r]=bi_z; an_[r]=bi_n; br[r]=bh_r; bz[r]=bh_z; bn[r]=bh_n;
    }
    #pragma unroll 4
    for (int j = 0; j < HH; j++) {
        const float wr = g_WihT[j*H3 + h];
        const float wz = g_WihT[j*H3 + HH + h];
        const float wn = g_WihT[j*H3 + 2*HH + h];
        const float vr = g_WhhT[j*H3 + h];
        const float vz = g_WhhT[j*H3 + HH + h];
        const float vn = g_WhhT[j*H3 + 2*HH + h];
        #pragma unroll
        for (int r = 0; r < 8; r++) {
            const float x = xs[r][j], hh = hs[r][j];
            ar[r]  = fmaf(x,  wr, ar[r]);
            az[r]  = fmaf(x,  wz, az[r]);
            an_[r] = fmaf(x,  wn, an_[r]);
            br[r]  = fmaf(hh, vr, br[r]);
            bz[r]  = fmaf(hh, vz, bz[r]);
            bn[r]  = fmaf(hh, vn, bn[r]);
        }
    }
    float hnew[8];
    #pragma unroll
    for (int r = 0; r < 8; r++) {
        const float rr = 1.0f / (1.0f + expf(-(ar[r] + br[r])));
        const float zz = 1.0f / (1.0f + expf(-(az[r] + bz[r])));
        const float nv = tanhf(an_[r] + rr * bn[r]);
        const float hp = (1.0f - zz) * nv + zz * hs[r][h];
        hnew[r] = hp;
        g_state[(nb + r)*HH + h] = hp;
    }
    __syncthreads();                // everyone done reading xs
    #pragma unroll
    for (int r = 0; r < 8; r++) xs[r][h] = hnew[r];
    __syncthreads();

    float q[8];
    #pragma unroll
    for (int r = 0; r < 8; r++) q[r] = 0.0f;
    #pragma unroll 4
    for (int j = 0; j < HH; j++) {
        const float wq = g_WqT[j*HH + h];
        #pragma unroll
        for (int r = 0; r < 8; r++) q[r] = fmaf(xs[r][j], wq, q[r]);
    }
    #pragma unroll
    for (int r = 0; r < 8; r++) g_q[(nb + r)*HH + h] = q[r];
}

// fast tanh: exact identity, approx MUFU exp+rcp; ABS error ~2e-6 (safe for argmax)
__device__ __forceinline__ float tanh_fast(float x) {
    float u = __expf(2.0f * x);
    return 1.0f - __fdividef(2.0f, u + 1.0f);
}

// ---------------- fused attention: k = E@Wk^T, logits = w·tanh(q+k) -----
#define ATTN_SMEM ((HH*HH + 64*HH + 2*HH) * 4)

__global__ void attn_kernel(const float* __restrict__ enc_out,
                            const float* __restrict__ w_score) {
    extern __shared__ float sm[];
    float* Wt = sm;                 // [128][128]  Wt[h][o] = Wk[o][h]
    float* Es = sm + HH*HH;         // [64][128]
    float* qs = Es + 64*HH;         // [128]
    float* ws = qs + HH;            // [128]

    const int tid  = threadIdx.x;   // 256 threads
    const int w    = tid >> 5;      // warp 0..7: rows w*8..w*8+7
    const int lane = tid & 31;      // cols lane*4..lane*4+3

    for (int i = tid; i < HH*HH; i += 256) Wt[i] = g_WkT[i];
    if (tid < HH) ws[tid] = w_score[tid];

    const int TILES = (NN * LL) / 64;   // 32768
    for (int tile = blockIdx.x; tile < TILES; tile += gridDim.x) {
        const int row0 = tile * 64;
        const int n    = row0 >> 11;    // row0 / LL
        __syncthreads();
        if (tid < HH) qs[tid] = g_q[n*HH + tid];
        {   // tile is contiguous in memory: straight float4 copy
            const float4* src = (const float4*)(enc_out + (size_t)row0 * HH);
            float4* dst = (float4*)Es;
            #pragma unroll
            for (int i = 0; i < 8; i++) dst[tid + i*256] = src[tid + i*256];
        }
        __syncthreads();

        float acc[8][4];
        #pragma unroll
        for (int i = 0; i < 8; i++)
            #pragma unroll
            for (int j = 0; j < 4; j++) acc[i][j] = 0.0f;

        #pragma unroll 1
        for (int k4 = 0; k4 < 32; k4++) {
            const float4 w0 = *(const float4*)&Wt[(4*k4+0)*HH + lane*4];
            const float4 w1 = *(const float4*)&Wt[(4*k4+1)*HH + lane*4];
            const float4 w2 = *(const float4*)&Wt[(4*k4+2)*HH + lane*4];
            const float4 w3 = *(const float4*)&Wt[(4*k4+3)*HH + lane*4];
            #pragma unroll
            for (int i = 0; i < 8; i++) {
                const float4 e = *(const float4*)&Es[(w*8+i)*HH + 4*k4];
                acc[i][0] = fmaf(e.x, w0.x, acc[i][0]);
                acc[i][0] = fmaf(e.y, w1.x, acc[i][0]);
                acc[i][0] = fmaf(e.z, w2.x, acc[i][0]);
                acc[i][0] = fmaf(e.w, w3.x, acc[i][0]);
                acc[i][1] = fmaf(e.x, w0.y, acc[i][1]);
                acc[i][1] = fmaf(e.y, w1.y, acc[i][1]);
                acc[i][1] = fmaf(e.z, w2.y, acc[i][1]);
                acc[i][1] = fmaf(e.w, w3.y, acc[i][1]);
                acc[i][2] = fmaf(e.x, w0.z, acc[i][2]);
                acc[i][2] = fmaf(e.y, w1.z, acc[i][2]);
                acc[i][2] = fmaf(e.z, w2.z, acc[i][2]);
                acc[i][2] = fmaf(e.w, w3.z, acc[i][2]);
                acc[i][3] = fmaf(e.x, w0.w, acc[i][3]);
                acc[i][3] = fmaf(e.y, w1.w, acc[i][3]);
                acc[i][3] = fmaf(e.z, w2.w, acc[i][3]);
                acc[i][3] = fmaf(e.w, w3.w, acc[i][3]);
            }
        }

        const float4 q4 = *(const float4*)&qs[lane*4];
        const float4 s4 = *(const float4*)&ws[lane*4];
        #pragma unroll
        for (int i = 0; i < 8; i++) {
            float p = s4.x * tanh_fast(q4.x + acc[i][0])
                    + s4.y * tanh_fast(q4.y + acc[i][1])
                    + s4.z * tanh_fast(q4.z + acc[i][2])
                    + s4.w * tanh_fast(q4.w + acc[i][3]);
            p += __shfl_xor_sync(0xffffffff, p, 16);
            p += __shfl_xor_sync(0xffffffff, p, 8);
            p += __shfl_xor_sync(0xffffffff, p, 4);
            p += __shfl_xor_sync(0xffffffff, p, 2);
            p += __shfl_xor_sync(0xffffffff, p, 1);
            if (lane == 0) g_logits[row0 + w*8 + i] = p;
        }
    }
}

// ---------------- softmax + argmax + gather next decoder input -----------
__global__ void softmax_kernel(const float* __restrict__ enc_in,
                               float* __restrict__ out, int step) {
    const int n = blockIdx.x;
    const int tid = threadIdx.x;    // 256
    __shared__ float sv[256];
    __shared__ int   si[256];
    const float* lg = g_logits + (size_t)n * LL;

    float m = -1e30f; int mi = 0;
    for (int l = tid; l < LL; l += 256) {
        const float v = lg[l];
        if (v > m) { m = v; mi = l; }
    }
    sv[tid] = m; si[tid] = mi;
    __syncthreads();
    for (int s = 128; s > 0; s >>= 1) {
        if (tid < s) {
            const float v2 = sv[tid+s]; const int i2 = si[tid+s];
            if (v2 > sv[tid] || (v2 == sv[tid] && i2 < si[tid])) {
                sv[tid] = v2; si[tid] = i2;
            }
        }
        __syncthreads();
    }
    m = sv[0]; mi = si[0];
    __syncthreads();

    float s = 0.0f;
    for (int l = tid; l < LL; l += 256) s += __expf(lg[l] - m);
    sv[tid] = s;
    __syncthreads();
    for (int st = 128; st > 0; st >>= 1) {
        if (tid < st) sv[tid] += sv[tid+st];
        __syncthreads();
    }
    const float inv = 1.0f / sv[0];

    float* o = out + (size_t)n * STEPS * LL + (size_t)step * LL;
    for (int l = tid; l < LL; l += 256) o[l] = __expf(lg[l] - m) * inv;

    if (tid < HH)
        g_x[n*HH + tid] = enc_in[((size_t)n * LL + mi) * HH + tid];
}

// ---------------- launch ----------------
extern "C" void kernel_launch(void* const* d_in, const int* in_sizes, int n_in,
                              void* d_out, int out_size) {
    const float* enc_in  = (const float*)d_in[0];
    const float* enc_out = (const float*)d_in[1];
    const float* state   = (const float*)d_in[2];
    const float* W_ih    = (const float*)d_in[3];
    const float* W_hh    = (const float*)d_in[4];
    const float* b_ih    = (const float*)d_in[5];
    const float* b_hh    = (const float*)d_in[6];
    const float* Wq      = (const float*)d_in[7];
    const float* Wk      = (const float*)d_in[8];
    const float* w_score = (const float*)d_in[9];
    float* out = (float*)d_out;

    cudaFuncSetAttribute(attn_kernel,
                         cudaFuncAttributeMaxDynamicSharedMemorySize, ATTN_SMEM);

    init_kernel<<<256, 256>>>(state, W_ih, W_hh, Wq, Wk);
    for (int step = 0; step < STEPS; step++) {
        gru_q_kernel<<<NN/8, HH>>>(b_ih, b_hh);
        attn_kernel<<<2048, 256, ATTN_SMEM>>>(enc_out, w_score);
        softmax_kernel<<<NN, 256>>>(enc_in, out, step);
    }
}

// round 5
// speedup vs baseline: 2.6381x; 2.6381x over previous
#include <cuda_runtime.h>
#include <cuda_fp16.h>
#include <math.h>

#define NN 1024
#define LL 2048
#define HH 128
#define H3 384
#define STEPS 2
#define ROWS_TOT (NN*LL)
#define TILES (ROWS_TOT/128)

// ---------------- device scratch ----------------
__device__ float g_k[(size_t)ROWS_TOT * HH];   // 1 GB: k = enc_out @ Wk^T
__device__ float g_x[NN*HH];
__device__ float g_state[NN*HH];
__device__ float g_q[NN*HH];
__device__ float g_logits[ROWS_TOT];
__device__ float g_WihT[HH*H3];
__device__ float g_WhhT[HH*H3];
__device__ float g_WqT[HH*HH];

__device__ __forceinline__ unsigned pack_h2(__half a, __half b) {
    __half2 h = __halves2half2(a, b);
    return *reinterpret_cast<unsigned*>(&h);
}
__device__ __forceinline__ float tanh_fast(float x) {
    float u = __expf(2.0f * x);
    return 1.0f - __fdividef(2.0f, u + 1.0f);
}

#define MMA(c, a, b0_, b1_) \
    asm volatile("mma.sync.aligned.m16n8k16.row.col.f32.f16.f16.f32 " \
        "{%0,%1,%2,%3}, {%4,%5,%6,%7}, {%8,%9}, {%0,%1,%2,%3};" \
        : "+f"(c[0]), "+f"(c[1]), "+f"(c[2]), "+f"(c[3]) \
        : "r"(a[0]), "r"(a[1]), "r"(a[2]), "r"(a[3]), "r"(b0_), "r"(b1_))

// ---------------- init ----------------
__global__ void init_kernel(const float* __restrict__ state,
                            const float* __restrict__ W_ih,
                            const float* __restrict__ W_hh,
                            const float* __restrict__ Wq) {
    int i = blockIdx.x * blockDim.x + threadIdx.x;
    int stride = gridDim.x * blockDim.x;
    for (int idx = i; idx < NN*HH; idx += stride) {
        g_x[idx] = 1.0f;
        g_state[idx] = state[idx];
    }
    for (int idx = i; idx < H3*HH; idx += stride) {
        int gq = idx / HH, j = idx % HH;
        g_WihT[j*H3 + gq] = W_ih[idx];
        g_WhhT[j*H3 + gq] = W_hh[idx];
    }
    for (int idx = i; idx < HH*HH; idx += stride) {
        int h = idx / HH, j = idx % HH;
        g_WqT[j*HH + h] = Wq[idx];
    }
}

// ---------------- GRU + q projection ----------------
__global__ void gru_q_kernel(const float* __restrict__ b_ih,
                             const float* __restrict__ b_hh) {
    const int h  = threadIdx.x;
    const int nb = blockIdx.x * 8;
    __shared__ float xs[8][HH];
    __shared__ float hs[8][HH];
    #pragma unroll
    for (int r = 0; r < 8; r++) {
        xs[r][h] = g_x[(nb + r)*HH + h];
        hs[r][h] = g_state[(nb + r)*HH + h];
    }
    __syncthreads();

    float ar[8], az[8], an_[8], br[8], bz[8], bn[8];
    const float bi_r = b_ih[h], bi_z = b_ih[HH+h], bi_n = b_ih[2*HH+h];
    const float bh_r = b_hh[h], bh_z = b_hh[HH+h], bh_n = b_hh[2*HH+h];
    #pragma unroll
    for (int r = 0; r < 8; r++) {
        ar[r]=bi_r; az[r]=bi_z; an_[r]=bi_n; br[r]=bh_r; bz[r]=bh_z; bn[r]=bh_n;
    }
    #pragma unroll 4
    for (int j = 0; j < HH; j++) {
        const float wr = g_WihT[j*H3 + h];
        const float wz = g_WihT[j*H3 + HH + h];
        const float wn = g_WihT[j*H3 + 2*HH + h];
        const float vr = g_WhhT[j*H3 + h];
        const float vz = g_WhhT[j*H3 + HH + h];
        const float vn = g_WhhT[j*H3 + 2*HH + h];
        #pragma unroll
        for (int r = 0; r < 8; r++) {
            const float x = xs[r][j], hh = hs[r][j];
            ar[r]  = fmaf(x,  wr, ar[r]);
            az[r]  = fmaf(x,  wz, az[r]);
            an_[r] = fmaf(x,  wn, an_[r]);
            br[r]  = fmaf(hh, vr, br[r]);
            bz[r]  = fmaf(hh, vz, bz[r]);
            bn[r]  = fmaf(hh, vn, bn[r]);
        }
    }
    float hnew[8];
    #pragma unroll
    for (int r = 0; r < 8; r++) {
        const float rr = 1.0f / (1.0f + expf(-(ar[r] + br[r])));
        const float zz = 1.0f / (1.0f + expf(-(az[r] + bz[r])));
        const float nv = tanhf(an_[r] + rr * bn[r]);
        const float hp = (1.0f - zz) * nv + zz * hs[r][h];
        hnew[r] = hp;
        g_state[(nb + r)*HH + h] = hp;
    }
    __syncthreads();
    #pragma unroll
    for (int r = 0; r < 8; r++) xs[r][h] = hnew[r];
    __syncthreads();

    float q[8];
    #pragma unroll
    for (int r = 0; r < 8; r++) q[r] = 0.0f;
    #pragma unroll 4
    for (int j = 0; j < HH; j++) {
        const float wq = g_WqT[j*HH + h];
        #pragma unroll
        for (int r = 0; r < 8; r++) q[r] = fmaf(xs[r][j], wq, q[r]);
    }
    #pragma unroll
    for (int r = 0; r < 8; r++) g_q[(nb + r)*HH + h] = q[r];
}

// ---------------- fused GEMM: k = E@Wk^T (store) + step-1 logits ----------------
// smem: Bhi/Blo [64][136] u32, Ahi/Alo [128][68] u32, qs/ws [128] f32, part [128][2]
#define SM_BHI  0
#define SM_BLO  34816
#define SM_AHI  69632
#define SM_ALO  104448
#define SM_QS   139264
#define SM_WS   139776
#define SM_PART 140288
#define KG_SMEM 141312

__global__ void __launch_bounds__(256, 1)
kgemm_kernel(const float* __restrict__ enc_out,
             const float* __restrict__ Wk,
             const float* __restrict__ w_score) {
    extern __shared__ char sm[];
    unsigned* Bhi = (unsigned*)(sm + SM_BHI);
    unsigned* Blo = (unsigned*)(sm + SM_BLO);
    unsigned* Ahi = (unsigned*)(sm + SM_AHI);
    unsigned* Alo = (unsigned*)(sm + SM_ALO);
    float* qs   = (float*)(sm + SM_QS);
    float* ws   = (float*)(sm + SM_WS);
    float* part = (float*)(sm + SM_PART);

    const int tid  = threadIdx.x;
    const int wid  = tid >> 5, lane = tid & 31;
    const int g    = lane >> 2, tg = lane & 3;
    const int wr   = (wid >> 1) * 32;     // warp row base (0..96)
    const int wc   = (wid & 1) * 64;      // warp col base (0 or 64)

    // B = Wk^T, hi/lo fp16, packed 2-along-k: Bhi[k2][n] = {Wk[n][2k2], Wk[n][2k2+1]}
    for (int i = tid; i < 64*HH; i += 256) {
        int n = i >> 6, k2 = i & 63;
        float2 v = *(const float2*)&Wk[n*HH + 2*k2];
        __half hx = __float2half_rn(v.x), hy = __float2half_rn(v.y);
        float rx = v.x - __half2float(hx), ry = v.y - __half2float(hy);
        Bhi[k2*136 + n] = pack_h2(hx, hy);
        Blo[k2*136 + n] = pack_h2(__float2half_rn(rx), __float2half_rn(ry));
    }
    if (tid < HH) ws[tid] = w_score[tid];

    for (int t = blockIdx.x; t < TILES; t += gridDim.x) {
        const int n_idx = t >> 4;           // batch index (16 tiles per row of L)
        __syncthreads();                    // prev epilogue done (part/qs free)

        // load + split A tile (128 rows x 128 k)
        const float* src = enc_out + (size_t)t * 128 * HH;
        #pragma unroll
        for (int i = 0; i < 32; i++) {
            int idx = tid + i*256;
            int r = idx >> 6, k2 = idx & 63;
            float2 v = *(const float2*)&src[r*HH + 2*k2];
            __half hx = __float2half_rn(v.x), hy = __float2half_rn(v.y);
            float rx = v.x - __half2float(hx), ry = v.y - __half2float(hy);
            Ahi[r*68 + k2] = pack_h2(hx, hy);
            Alo[r*68 + k2] = pack_h2(__float2half_rn(rx), __float2half_rn(ry));
        }
        if (tid < HH) qs[tid] = g_q[n_idx*HH + tid];
        __syncthreads();

        float acc[2][8][4];
        #pragma unroll
        for (int mf = 0; mf < 2; mf++)
            #pragma unroll
            for (int nf = 0; nf < 8; nf++)
                #pragma unroll
                for (int j = 0; j < 4; j++) acc[mf][nf][j] = 0.0f;

        #pragma unroll 2
        for (int ks = 0; ks < 8; ks++) {
            unsigned ah[2][4], al[2][4];
            #pragma unroll
            for (int mf = 0; mf < 2; mf++) {
                const int r0 = (wr + 16*mf + g) * 68 + 8*ks + tg;
                const int r1 = r0 + 8*68;
                ah[mf][0] = Ahi[r0];     ah[mf][1] = Ahi[r1];
                ah[mf][2] = Ahi[r0 + 4]; ah[mf][3] = Ahi[r1 + 4];
                al[mf][0] = Alo[r0];     al[mf][1] = Alo[r1];
                al[mf][2] = Alo[r0 + 4]; al[mf][3] = Alo[r1 + 4];
            }
            #pragma unroll
            for (int nf = 0; nf < 8; nf++) {
                const int nc = wc + 8*nf + g;
                const unsigned bh0 = Bhi[(8*ks+tg)*136 + nc];
                const unsigned bh1 = Bhi[(8*ks+tg+4)*136 + nc];
                const unsigned bl0 = Blo[(8*ks+tg)*136 + nc];
                const unsigned bl1 = Blo[(8*ks+tg+4)*136 + nc];
                #pragma unroll
                for (int mf = 0; mf < 2; mf++) {
                    MMA(acc[mf][nf], ah[mf], bh0, bh1);   // hi*hi
                    MMA(acc[mf][nf], al[mf], bh0, bh1);   // lo*hi
                    MMA(acc[mf][nf], ah[mf], bl0, bl1);   // hi*lo
                }
            }
        }

        // epilogue: store k (fp32) + step-1 logit partials
        float qv0[8], qv1[8], wv0[8], wv1[8];
        #pragma unroll
        for (int nf = 0; nf < 8; nf++) {
            const int c = wc + 8*nf + 2*tg;
            qv0[nf] = qs[c]; qv1[nf] = qs[c+1];
            wv0[nf] = ws[c]; wv1[nf] = ws[c+1];
        }
        float* kout = g_k + (size_t)t * 128 * HH;
        float p0[2] = {0.0f, 0.0f}, p1[2] = {0.0f, 0.0f};
        #pragma unroll
        for (int mf = 0; mf < 2; mf++) {
            const int row0 = wr + 16*mf + g;
            #pragma unroll
            for (int nf = 0; nf < 8; nf++) {
                const int c = wc + 8*nf + 2*tg;
                float* a = acc[mf][nf];
                *(float2*)&kout[(size_t)row0*HH + c]     = make_float2(a[0], a[1]);
                *(float2*)&kout[(size_t)(row0+8)*HH + c] = make_float2(a[2], a[3]);
                p0[mf] += wv0[nf]*tanh_fast(qv0[nf]+a[0]) + wv1[nf]*tanh_fast(qv1[nf]+a[1]);
                p1[mf] += wv0[nf]*tanh_fast(qv0[nf]+a[2]) + wv1[nf]*tanh_fast(qv1[nf]+a[3]);
            }
        }
        #pragma unroll
        for (int mf = 0; mf < 2; mf++) {
            p0[mf] += __shfl_xor_sync(~0u, p0[mf], 1);
            p0[mf] += __shfl_xor_sync(~0u, p0[mf], 2);
            p1[mf] += __shfl_xor_sync(~0u, p1[mf], 1);
            p1[mf] += __shfl_xor_sync(~0u, p1[mf], 2);
            if (tg == 0) {
                part[(wr + 16*mf + g)*2     + (wid & 1)] = p0[mf];
                part[(wr + 16*mf + g + 8)*2 + (wid & 1)] = p1[mf];
            }
        }
        __syncthreads();
        if (tid < 128) g_logits[t*128 + tid] = part[tid*2] + part[tid*2 + 1];
    }
}

// ---------------- step-2: stream k, compute logits ----------------
__global__ void logits_stream_kernel(const float* __restrict__ w_score) {
    const int lane  = threadIdx.x & 31;
    const int wglob = (blockIdx.x * blockDim.x + threadIdx.x) >> 5;
    const int nw    = (gridDim.x * blockDim.x) >> 5;
    const float4 wv = ((const float4*)w_score)[lane];
    for (int row = wglob; row < ROWS_TOT; row += nw) {
        const int n = row >> 11;
        const float4 kv = *(const float4*)&g_k[(size_t)row*HH + lane*4];
        const float4 qv = *(const float4*)&g_q[n*HH + lane*4];
        float p = wv.x * tanh_fast(qv.x + kv.x)
                + wv.y * tanh_fast(qv.y + kv.y)
                + wv.z * tanh_fast(qv.z + kv.z)
                + wv.w * tanh_fast(qv.w + kv.w);
        p += __shfl_xor_sync(~0u, p, 16);
        p += __shfl_xor_sync(~0u, p, 8);
        p += __shfl_xor_sync(~0u, p, 4);
        p += __shfl_xor_sync(~0u, p, 2);
        p += __shfl_xor_sync(~0u, p, 1);
        if (lane == 0) g_logits[row] = p;
    }
}

// ---------------- softmax + argmax + gather ----------------
__global__ void softmax_kernel(const float* __restrict__ enc_in,
                               float* __restrict__ out, int step) {
    const int n = blockIdx.x;
    const int tid = threadIdx.x;
    __shared__ float sv[256];
    __shared__ int   si[256];
    const float* lg = g_logits + (size_t)n * LL;

    float m = -1e30f; int mi = 0;
    for (int l = tid; l < LL; l += 256) {
        const float v = lg[l];
        if (v > m) { m = v; mi = l; }
    }
    sv[tid] = m; si[tid] = mi;
    __syncthreads();
    for (int s = 128; s > 0; s >>= 1) {
        if (tid < s) {
            const float v2 = sv[tid+s]; const int i2 = si[tid+s];
            if (v2 > sv[tid] || (v2 == sv[tid] && i2 < si[tid])) {
                sv[tid] = v2; si[tid] = i2;
            }
        }
        __syncthreads();
    }
    m = sv[0]; mi = si[0];
    __syncthreads();

    float s = 0.0f;
    for (int l = tid; l < LL; l += 256) s += __expf(lg[l] - m);
    sv[tid] = s;
    __syncthreads();
    for (int st = 128; st > 0; st >>= 1) {
        if (tid < st) sv[tid] += sv[tid+st];
        __syncthreads();
    }
    const float inv = 1.0f / sv[0];

    float* o = out + (size_t)n * STEPS * LL + (size_t)step * LL;
    for (int l = tid; l < LL; l += 256) o[l] = __expf(lg[l] - m) * inv;

    if (tid < HH)
        g_x[n*HH + tid] = enc_in[((size_t)n * LL + mi) * HH + tid];
}

// ---------------- launch ----------------
extern "C" void kernel_launch(void* const* d_in, const int* in_sizes, int n_in,
                              void* d_out, int out_size) {
    const float* enc_in  = (const float*)d_in[0];
    const float* enc_out = (const float*)d_in[1];
    const float* state   = (const float*)d_in[2];
    const float* W_ih    = (const float*)d_in[3];
    const float* W_hh    = (const float*)d_in[4];
    const float* b_ih    = (const float*)d_in[5];
    const float* b_hh    = (const float*)d_in[6];
    const float* Wq      = (const float*)d_in[7];
    const float* Wk      = (const float*)d_in[8];
    const float* w_score = (const float*)d_in[9];
    float* out = (float*)d_out;

    cudaFuncSetAttribute(kgemm_kernel,
                         cudaFuncAttributeMaxDynamicSharedMemorySize, KG_SMEM);

    init_kernel<<<256, 256>>>(state, W_ih, W_hh, Wq);
    // step 1: GRU -> fused GEMM (k store + logits) -> softmax/gather
    gru_q_kernel<<<NN/8, HH>>>(b_ih, b_hh);
    kgemm_kernel<<<148, 256, KG_SMEM>>>(enc_out, Wk, w_score);
    softmax_kernel<<<NN, 256>>>(enc_in, out, 0);
    // step 2: GRU -> stream k -> softmax
    gru_q_kernel<<<NN/8, HH>>>(b_ih, b_hh);
    logits_stream_kernel<<<1184, 256>>>(w_score);
    softmax_kernel<<<NN, 256>>>(enc_in, out, 1);
}